// round 2
// baseline (speedup 1.0000x reference)
#include <cuda_runtime.h>
#include <cstdint>

// TransitionLayer: BN(eval)+ReLU+1x1conv(512->256)+avgpool2x2, NCHW fp32.
// pool(conv(act)) == conv(pool(act)) -> GEMM M=50176, K=512, N=256 (13.15 GFLOP).
// R2: 8m x 8n register tile, broadcast LDS.128 operand reads, FFMA2 math,
//     x-tile register prefetch across the barrier. Target: FMA-pipe bound.

#define BN_EPS 1e-5f

constexpr int NIMG = 64;
constexpr int CIN  = 512;
constexpr int HH   = 56;
constexpr int WW   = 56;
constexpr int COUT = 256;
constexpr int PP   = 28;
constexpr int PIX  = PP * PP;          // 784
constexpr int M_TOTAL = NIMG * PIX;    // 50176

constexpr int BM = 64;
constexpr int BK = 16;
constexpr int BN_PAD = 264;            // 256 + 8 pad, keeps rows 16B-aligned

__global__ __launch_bounds__(256, 2)
void transition_fused_kernel(const float* __restrict__ x,
                             const float* __restrict__ bn_w,
                             const float* __restrict__ bn_b,
                             const float* __restrict__ bn_m,
                             const float* __restrict__ bn_v,
                             const float* __restrict__ conv_w,
                             float* __restrict__ out)
{
    __shared__ float s_scale[CIN];
    __shared__ float s_shift[CIN];
    __shared__ __align__(16) float As[BK][BM];
    __shared__ __align__(16) float Bs[BK][BN_PAD];

    const int tid = threadIdx.x;

    for (int c = tid; c < CIN; c += 256) {
        float inv = rsqrtf(bn_v[c] + BN_EPS);
        float sc  = bn_w[c] * inv;
        s_scale[c] = sc;
        s_shift[c] = bn_b[c] - bn_m[c] * sc;
    }

    const int m0 = blockIdx.x * BM;

    // ---- A(x) load mapping: ml = pooled pixel in tile, ks = k phase (0..3)
    const int ml = tid & 63;
    const int ks = tid >> 6;
    const int m_load = m0 + ml;
    const int nimg_l = m_load / PIX;
    const int pix_l  = m_load % PIX;
    const int pi     = pix_l / PP;
    const int pj     = pix_l % PP;
    const float* xbase = x + ((size_t)(nimg_l * CIN) * HH + 2 * pi) * WW + 2 * pj;

    // ---- B load mapping
    const int olane = tid >> 2;        // 0..63
    const int kq    = (tid & 3) * 4;   // 0,4,8,12

    // ---- compute mapping: 8m x 8n per thread
    const int tm3 = tid & 7;           // m group: m_local = tm3*8 .. +7
    const int tn5 = tid >> 3;          // n group: o = tn5*8 .. +7

    unsigned long long acc[8][4];
    #pragma unroll
    for (int i = 0; i < 8; i++)
        #pragma unroll
        for (int p = 0; p < 4; p++) acc[i][p] = 0ULL;

    __syncthreads();   // BN tables ready

    // prologue: prefetch x tile 0 (raw)
    float2 r0[4], r1[4];
    #pragma unroll
    for (int j = 0; j < 4; j++) {
        const int c = 4 * j + ks;
        const float* xp = xbase + (size_t)c * (HH * WW);
        r0[j] = *reinterpret_cast<const float2*>(xp);
        r1[j] = *reinterpret_cast<const float2*>(xp + WW);
    }

    #pragma unroll 1
    for (int c0 = 0; c0 < CIN; c0 += BK) {
        // B tile: L2-resident weights
        float4 bv[4];
        #pragma unroll
        for (int pass = 0; pass < 4; pass++) {
            const int o = pass * 64 + olane;
            bv[pass] = *reinterpret_cast<const float4*>(conv_w + (size_t)o * CIN + c0 + kq);
        }
        // convert prefetched x -> pooled ReLU(BN) in As
        #pragma unroll
        for (int j = 0; j < 4; j++) {
            const int k = 4 * j + ks;
            const int c = c0 + k;
            float sc = s_scale[c], sh = s_shift[c];
            float v = fmaxf(fmaf(r0[j].x, sc, sh), 0.0f)
                    + fmaxf(fmaf(r0[j].y, sc, sh), 0.0f)
                    + fmaxf(fmaf(r1[j].x, sc, sh), 0.0f)
                    + fmaxf(fmaf(r1[j].y, sc, sh), 0.0f);
            As[k][ml] = 0.25f * v;
        }
        #pragma unroll
        for (int pass = 0; pass < 4; pass++) {
            const int o = pass * 64 + olane;
            Bs[kq + 0][o] = bv[pass].x;
            Bs[kq + 1][o] = bv[pass].y;
            Bs[kq + 2][o] = bv[pass].z;
            Bs[kq + 3][o] = bv[pass].w;
        }
        __syncthreads();

        // prefetch next x tile while computing this one
        if (c0 + BK < CIN) {
            #pragma unroll
            for (int j = 0; j < 4; j++) {
                const int c = c0 + BK + 4 * j + ks;
                const float* xp = xbase + (size_t)c * (HH * WW);
                r0[j] = *reinterpret_cast<const float2*>(xp);
                r1[j] = *reinterpret_cast<const float2*>(xp + WW);
            }
        }

        // ---- FFMA2 inner product, 8x8 tile ----
        #pragma unroll
        for (int k = 0; k < BK; k++) {
            float4 a0 = *reinterpret_cast<const float4*>(&As[k][tm3 * 8]);
            float4 a1 = *reinterpret_cast<const float4*>(&As[k][tm3 * 8 + 4]);
            uint4  b0 = *reinterpret_cast<const uint4*>(&Bs[k][tn5 * 8]);
            uint4  b1 = *reinterpret_cast<const uint4*>(&Bs[k][tn5 * 8 + 4]);
            unsigned long long B0, B1, B2, B3;
            asm("mov.b64 %0, {%1,%2};" : "=l"(B0) : "r"(b0.x), "r"(b0.y));
            asm("mov.b64 %0, {%1,%2};" : "=l"(B1) : "r"(b0.z), "r"(b0.w));
            asm("mov.b64 %0, {%1,%2};" : "=l"(B2) : "r"(b1.x), "r"(b1.y));
            asm("mov.b64 %0, {%1,%2};" : "=l"(B3) : "r"(b1.z), "r"(b1.w));
            float a[8] = {a0.x, a0.y, a0.z, a0.w, a1.x, a1.y, a1.z, a1.w};
            #pragma unroll
            for (int i = 0; i < 8; i++) {
                unsigned long long Ai;
                unsigned int au = __float_as_uint(a[i]);
                asm("mov.b64 %0, {%1,%2};" : "=l"(Ai) : "r"(au), "r"(au));
                asm("fma.rn.f32x2 %0, %1, %2, %0;" : "+l"(acc[i][0]) : "l"(Ai), "l"(B0));
                asm("fma.rn.f32x2 %0, %1, %2, %0;" : "+l"(acc[i][1]) : "l"(Ai), "l"(B1));
                asm("fma.rn.f32x2 %0, %1, %2, %0;" : "+l"(acc[i][2]) : "l"(Ai), "l"(B2));
                asm("fma.rn.f32x2 %0, %1, %2, %0;" : "+l"(acc[i][3]) : "l"(Ai), "l"(B3));
            }
        }
        __syncthreads();
    }

    // ---- Epilogue: per thread, 8 consecutive m per o -> 2x STG.128 per o ----
    const int m    = m0 + tm3 * 8;          // 8-aligned; 784%8==0 -> single image
    const int nimg = m / PIX;
    const int px   = m % PIX;
    float* ob = out + (size_t)nimg * (COUT * PIX) + px;
    const int obase = tn5 * 8;

    #pragma unroll
    for (int p = 0; p < 4; p++) {
        float lo[8], hi[8];
        #pragma unroll
        for (int i = 0; i < 8; i++) {
            unsigned int l, h;
            asm("mov.b64 {%0,%1}, %2;" : "=r"(l), "=r"(h) : "l"(acc[i][p]));
            lo[i] = __uint_as_float(l);
            hi[i] = __uint_as_float(h);
        }
        float* p0 = ob + (size_t)(obase + 2 * p) * PIX;
        float* p1 = ob + (size_t)(obase + 2 * p + 1) * PIX;
        *reinterpret_cast<float4*>(p0)     = make_float4(lo[0], lo[1], lo[2], lo[3]);
        *reinterpret_cast<float4*>(p0 + 4) = make_float4(lo[4], lo[5], lo[6], lo[7]);
        *reinterpret_cast<float4*>(p1)     = make_float4(hi[0], hi[1], hi[2], hi[3]);
        *reinterpret_cast<float4*>(p1 + 4) = make_float4(hi[4], hi[5], hi[6], hi[7]);
    }
}

extern "C" void kernel_launch(void* const* d_in, const int* in_sizes, int n_in,
                              void* d_out, int out_size)
{
    const float* x      = (const float*)d_in[0];
    const float* bn_w   = (const float*)d_in[1];
    const float* bn_b   = (const float*)d_in[2];
    const float* bn_m   = (const float*)d_in[3];
    const float* bn_v   = (const float*)d_in[4];
    const float* conv_w = (const float*)d_in[5];
    float* out = (float*)d_out;

    transition_fused_kernel<<<M_TOTAL / BM, 256>>>(x, bn_w, bn_b, bn_m, bn_v, conv_w, out);
}

// round 4
// speedup vs baseline: 1.5645x; 1.5645x over previous
#include <cuda_runtime.h>
#include <cuda_bf16.h>
#include <cstdint>

// TransitionLayer: BN(eval)+ReLU+1x1conv(512->256)+avgpool2x2, NCHW fp32.
// pool(conv(act)) == conv(pool(act)) -> GEMM M=50176, K=512, N=256.
// R4: mma.sync bf16 (base-PTX HMMA; tcgen05 is 'a'-gated and unavailable under
//     the harness's compute_103 virtual arch). 3-term hi/lo split for accuracy.
//     Tile: CTA 256thr = 8 warps (2m x 4n), M=64, N=256, BK=32, double buffer.

#define BN_EPS 1e-5f

constexpr int CIN  = 512;
constexpr int HH   = 56;
constexpr int WW   = 56;
constexpr int COUT = 256;
constexpr int PP   = 28;
constexpr int PIX  = PP * PP;           // 784
constexpr int M_TOTAL = 64 * PIX;       // 50176
constexpr int MT   = 64;                // m per CTA
constexpr int BK   = 32;                // k chunk
constexpr int NCH  = CIN / BK;          // 16

// smem tile rows: 36 words (144B) stride; [0,16) hi words, [16,32) lo, [32,36) pad
constexpr int RSW    = 36;
constexpr int LO_OFF = 16;
constexpr int A_WORDS = MT * RSW;              // 2304
constexpr int B_WORDS = COUT * RSW;            // 9216
constexpr int STAGE_WORDS = A_WORDS + B_WORDS; // 11520
constexpr int SM_TILE_OFF = 1024;              // after 512+512 scale/shift floats
constexpr int SM_TOTAL = (SM_TILE_OFF + 2 * STAGE_WORDS) * 4;  // 96256 B

#define MMA_BF16(C, A0, A1, A2, A3, B0, B1)                                  \
    asm volatile("mma.sync.aligned.m16n8k16.row.col.f32.bf16.bf16.f32 "      \
                 "{%0,%1,%2,%3}, {%4,%5,%6,%7}, {%8,%9}, {%0,%1,%2,%3};"     \
                 : "+f"((C)[0]), "+f"((C)[1]), "+f"((C)[2]), "+f"((C)[3])    \
                 : "r"(A0), "r"(A1), "r"(A2), "r"(A3), "r"(B0), "r"(B1))

__device__ __forceinline__ void split2(float v0, float v1, uint32_t& hi, uint32_t& lo) {
    __nv_bfloat16 h0 = __float2bfloat16_rn(v0);
    __nv_bfloat16 h1 = __float2bfloat16_rn(v1);
    float l0f = v0 - __bfloat162float(h0);
    float l1f = v1 - __bfloat162float(h1);
    __nv_bfloat16 l0 = __float2bfloat16_rn(l0f);
    __nv_bfloat16 l1 = __float2bfloat16_rn(l1f);
    hi = (uint32_t)__bfloat16_as_ushort(h0) | ((uint32_t)__bfloat16_as_ushort(h1) << 16);
    lo = (uint32_t)__bfloat16_as_ushort(l0) | ((uint32_t)__bfloat16_as_ushort(l1) << 16);
}

__global__ __launch_bounds__(256, 1)
void transition_hmma_kernel(const float* __restrict__ x,
                            const float* __restrict__ bn_w,
                            const float* __restrict__ bn_b,
                            const float* __restrict__ bn_m,
                            const float* __restrict__ bn_v,
                            const float* __restrict__ conv_w,
                            float* __restrict__ out)
{
    extern __shared__ __align__(16) uint32_t sm[];
    float* s_scale = reinterpret_cast<float*>(sm);
    float* s_shift = reinterpret_cast<float*>(sm) + 512;
    uint32_t* tiles = sm + SM_TILE_OFF;

    const int tid  = threadIdx.x;
    const int wid  = tid >> 5;
    const int lane = tid & 31;
    const int wm   = wid & 1;      // warp m: rows wm*32 .. +32
    const int wn   = wid >> 1;     // warp n: cols wn*64 .. +64

    for (int c = tid; c < CIN; c += 256) {
        float inv = rsqrtf(bn_v[c] + BN_EPS);
        float sc  = bn_w[c] * inv;
        s_scale[c] = sc;
        s_shift[c] = bn_b[c] - bn_m[c] * sc;
    }

    const int m0 = blockIdx.x * MT;

    // ---- A producer mapping: px = tid>>2 (one of 64 rows), q = tid&3 -> 8 channels
    const int pxl = tid >> 2;
    const int aq  = tid & 3;
    const int mg  = m0 + pxl;
    const int img = mg / PIX;
    const int pr  = mg % PIX;
    const float* xb = x + (size_t)img * (CIN * HH * WW)
                        + (size_t)(2 * (pr / PP)) * WW + 2 * (pr % PP);

    // ---- B producer mapping: 8 lanes per row, 8 row-passes
    const int bo = tid >> 3;       // row base 0..31
    const int bl = tid & 7;        // 4 floats each

    float2 ar0[8], ar1[8];
    float4 bw[8];

    float acc[2][8][4];
    #pragma unroll
    for (int mh = 0; mh < 2; mh++)
        #pragma unroll
        for (int nn = 0; nn < 8; nn++)
            #pragma unroll
            for (int e = 0; e < 4; e++) acc[mh][nn][e] = 0.0f;

    __syncthreads();   // BN tables

    // ---------- helpers as macros-by-structure ----------
    auto ldg_chunk = [&](int c0) {
        #pragma unroll
        for (int e = 0; e < 8; e++) {
            const int c = c0 + aq * 8 + e;
            const float* xp = xb + (size_t)c * (HH * WW);
            ar0[e] = *reinterpret_cast<const float2*>(xp);
            ar1[e] = *reinterpret_cast<const float2*>(xp + WW);
        }
        #pragma unroll
        for (int p = 0; p < 8; p++) {
            const int o = bo + p * 32;
            bw[p] = *reinterpret_cast<const float4*>(conv_w + (size_t)o * CIN + c0 + bl * 4);
        }
    };

    auto sts_chunk = [&](int c0, uint32_t* st) {
        // A: pooled ReLU(BN) -> split -> one 16B hi store + one 16B lo store
        uint32_t hiw[4], low[4];
        #pragma unroll
        for (int j = 0; j < 4; j++) {
            float v[2];
            #pragma unroll
            for (int t = 0; t < 2; t++) {
                const int e = 2 * j + t;
                const int c = c0 + aq * 8 + e;
                const float sc = s_scale[c], sh = s_shift[c];
                v[t] = 0.25f * (fmaxf(fmaf(ar0[e].x, sc, sh), 0.0f)
                              + fmaxf(fmaf(ar0[e].y, sc, sh), 0.0f)
                              + fmaxf(fmaf(ar1[e].x, sc, sh), 0.0f)
                              + fmaxf(fmaf(ar1[e].y, sc, sh), 0.0f));
            }
            split2(v[0], v[1], hiw[j], low[j]);
        }
        uint32_t* arow = st + pxl * RSW + aq * 4;
        *reinterpret_cast<uint4*>(arow) = make_uint4(hiw[0], hiw[1], hiw[2], hiw[3]);
        *reinterpret_cast<uint4*>(arow + LO_OFF) = make_uint4(low[0], low[1], low[2], low[3]);
        // B
        #pragma unroll
        for (int p = 0; p < 8; p++) {
            const int o = bo + p * 32;
            uint32_t h0, l0, h1, l1;
            split2(bw[p].x, bw[p].y, h0, l0);
            split2(bw[p].z, bw[p].w, h1, l1);
            uint32_t* brow = st + A_WORDS + o * RSW + bl * 2;
            brow[0] = h0; brow[1] = h1;
            brow[LO_OFF] = l0; brow[LO_OFF + 1] = l1;
        }
    };

    const int fr = lane >> 2;        // frag row / col-in-8
    const int fq = lane & 3;         // frag quad

    auto compute = [&](const uint32_t* st) {
        const uint32_t* A = st;
        const uint32_t* B = st + A_WORDS;
        #pragma unroll
        for (int ks = 0; ks < 2; ks++) {
            const int kw = fq + ks * 8;
            uint32_t ah[2][4], al[2][4];
            #pragma unroll
            for (int mh = 0; mh < 2; mh++) {
                const uint32_t* ap  = A + (wm * 32 + mh * 16 + fr) * RSW + kw;
                const uint32_t* ap8 = ap + 8 * RSW;
                ah[mh][0] = ap[0];           ah[mh][2] = ap[4];
                ah[mh][1] = ap8[0];          ah[mh][3] = ap8[4];
                al[mh][0] = ap[LO_OFF];      al[mh][2] = ap[LO_OFF + 4];
                al[mh][1] = ap8[LO_OFF];     al[mh][3] = ap8[LO_OFF + 4];
            }
            #pragma unroll
            for (int nn = 0; nn < 8; nn++) {
                const uint32_t* bp = B + (wn * 64 + nn * 8 + fr) * RSW + kw;
                const uint32_t bh0 = bp[0],      bh1 = bp[4];
                const uint32_t bl0 = bp[LO_OFF], bl1 = bp[LO_OFF + 4];
                #pragma unroll
                for (int mh = 0; mh < 2; mh++) {
                    MMA_BF16(acc[mh][nn], ah[mh][0], ah[mh][1], ah[mh][2], ah[mh][3], bh0, bh1);
                    MMA_BF16(acc[mh][nn], ah[mh][0], ah[mh][1], ah[mh][2], ah[mh][3], bl0, bl1);
                    MMA_BF16(acc[mh][nn], al[mh][0], al[mh][1], al[mh][2], al[mh][3], bh0, bh1);
                }
            }
        }
    };

    // ---------- pipelined main loop ----------
    ldg_chunk(0);
    sts_chunk(0, tiles);
    __syncthreads();

    #pragma unroll 1
    for (int i = 0; i < NCH; i++) {
        uint32_t* cur = tiles + (i & 1) * STAGE_WORDS;
        uint32_t* nxt = tiles + ((i + 1) & 1) * STAGE_WORDS;
        if (i + 1 < NCH) ldg_chunk((i + 1) * BK);
        compute(cur);
        if (i + 1 < NCH) sts_chunk((i + 1) * BK, nxt);
        __syncthreads();
    }

    // ---------- epilogue: out[img][o][pix] ----------
    const int q2 = fq * 2;
    #pragma unroll
    for (int mh = 0; mh < 2; mh++) {
        #pragma unroll
        for (int half = 0; half < 2; half++) {
            const int m  = m0 + wm * 32 + mh * 16 + fr + half * 8;
            const int im = m / PIX;
            const int px = m % PIX;
            float* ob = out + (size_t)im * (COUT * PIX) + px;
            #pragma unroll
            for (int nn = 0; nn < 8; nn++) {
                const int n = wn * 64 + nn * 8 + q2;
                ob[(size_t)n * PIX]       = acc[mh][nn][half * 2];
                ob[(size_t)(n + 1) * PIX] = acc[mh][nn][half * 2 + 1];
            }
        }
    }
}

extern "C" void kernel_launch(void* const* d_in, const int* in_sizes, int n_in,
                              void* d_out, int out_size)
{
    const float* x      = (const float*)d_in[0];
    const float* bn_w   = (const float*)d_in[1];
    const float* bn_b   = (const float*)d_in[2];
    const float* bn_m   = (const float*)d_in[3];
    const float* bn_v   = (const float*)d_in[4];
    const float* conv_w = (const float*)d_in[5];
    float* out = (float*)d_out;

    cudaFuncSetAttribute(transition_hmma_kernel,
                         cudaFuncAttributeMaxDynamicSharedMemorySize, SM_TOTAL);
    transition_hmma_kernel<<<M_TOTAL / MT, 256, SM_TOTAL>>>(
        x, bn_w, bn_b, bn_m, bn_v, conv_w, out);
}

// round 5
// speedup vs baseline: 1.7927x; 1.1458x over previous
#include <cuda_runtime.h>
#include <cuda_bf16.h>
#include <cstdint>

// TransitionLayer: BN(eval)+ReLU+1x1conv(512->256)+avgpool2x2, NCHW fp32.
// pool(conv(act)) == conv(pool(act)) -> GEMM M=50176, K=512, N=256.
// R5: HMMA bf16 3-term split; 2 CTAs/SM (<=128 regs), ldmatrix.x4 frag loads,
//     streaming producer (no chunk staging). Tile M=64 N=256 BK=32, dbl buffer.

#define BN_EPS 1e-5f

constexpr int CIN  = 512;
constexpr int HH   = 56;
constexpr int WW   = 56;
constexpr int COUT = 256;
constexpr int PP   = 28;
constexpr int PIX  = PP * PP;           // 784
constexpr int M_TOTAL = 64 * PIX;       // 50176
constexpr int MT   = 64;
constexpr int BK   = 32;
constexpr int NCH  = CIN / BK;          // 16

// row = 36 words (144B): [0,16) hi (32 bf16 = k0..31), [16,32) lo, [32,36) pad
constexpr int RSW_B   = 144;                    // row stride bytes
constexpr int LO_B    = 64;                     // lo offset bytes
constexpr int A_BYTES = MT * RSW_B;             // 9216
constexpr int B_BYTES = COUT * RSW_B;           // 36864
constexpr int STAGE_B = A_BYTES + B_BYTES;      // 46080
constexpr int TILE_OFF = 4096;                  // scale/shift tables
constexpr int SM_TOTAL = TILE_OFF + 2 * STAGE_B; // 96256

#define MMA_BF16(C, A, B0, B1)                                               \
    asm volatile("mma.sync.aligned.m16n8k16.row.col.f32.bf16.bf16.f32 "      \
                 "{%0,%1,%2,%3}, {%4,%5,%6,%7}, {%8,%9}, {%0,%1,%2,%3};"     \
                 : "+f"((C)[0]), "+f"((C)[1]), "+f"((C)[2]), "+f"((C)[3])    \
                 : "r"((A)[0]), "r"((A)[1]), "r"((A)[2]), "r"((A)[3]),       \
                   "r"(B0), "r"(B1))

#define LDMX4(R, ADDR)                                                       \
    asm volatile("ldmatrix.sync.aligned.m8n8.x4.shared.b16 {%0,%1,%2,%3}, [%4];" \
                 : "=r"((R)[0]), "=r"((R)[1]), "=r"((R)[2]), "=r"((R)[3])    \
                 : "r"(ADDR))

__device__ __forceinline__ uint32_t smem_u32(const void* p) {
    uint32_t a;
    asm("{ .reg .u64 t; cvta.to.shared.u64 t, %1; cvt.u32.u64 %0, t; }" : "=r"(a) : "l"(p));
    return a;
}
__device__ __forceinline__ void split2(float v0, float v1, uint32_t& hi, uint32_t& lo) {
    __nv_bfloat16 h0 = __float2bfloat16_rn(v0);
    __nv_bfloat16 h1 = __float2bfloat16_rn(v1);
    __nv_bfloat16 l0 = __float2bfloat16_rn(v0 - __bfloat162float(h0));
    __nv_bfloat16 l1 = __float2bfloat16_rn(v1 - __bfloat162float(h1));
    hi = (uint32_t)__bfloat16_as_ushort(h0) | ((uint32_t)__bfloat16_as_ushort(h1) << 16);
    lo = (uint32_t)__bfloat16_as_ushort(l0) | ((uint32_t)__bfloat16_as_ushort(l1) << 16);
}
__device__ __forceinline__ void sts64(uint32_t addr, uint32_t a, uint32_t b) {
    asm volatile("st.shared.v2.b32 [%0], {%1,%2};" :: "r"(addr), "r"(a), "r"(b) : "memory");
}

__global__ __launch_bounds__(256, 2)
void transition_hmma2_kernel(const float* __restrict__ x,
                             const float* __restrict__ bn_w,
                             const float* __restrict__ bn_b,
                             const float* __restrict__ bn_m,
                             const float* __restrict__ bn_v,
                             const float* __restrict__ conv_w,
                             float* __restrict__ out)
{
    extern __shared__ __align__(16) uint32_t sm[];
    float* s_scale = reinterpret_cast<float*>(sm);
    float* s_shift = reinterpret_cast<float*>(sm) + 512;
    const uint32_t sbase = smem_u32(sm);

    const int tid  = threadIdx.x;
    const int wid  = tid >> 5;
    const int lane = tid & 31;
    const int wm   = wid & 1;          // warp rows: wm*32 .. +32
    const int wn   = wid >> 1;         // warp cols: wn*64 .. +64

    for (int c = tid; c < CIN; c += 256) {
        float inv = rsqrtf(bn_v[c] + BN_EPS);
        float sc  = bn_w[c] * inv;
        s_scale[c] = sc;
        s_shift[c] = bn_b[c] - bn_m[c] * sc;
    }

    const int m0 = blockIdx.x * MT;

    // producer A mapping: pxl row (0..63), aq -> 8 channels
    const int pxl = tid >> 2;
    const int aq  = tid & 3;
    const int mg  = m0 + pxl;
    const int img = mg / PIX;
    const int pr  = mg % PIX;
    const float* xb = x + (size_t)img * (CIN * HH * WW)
                        + (size_t)(2 * (pr / PP)) * WW + 2 * (pr % PP);
    // producer B mapping: rows bo + p*32, k-floats [bl*4, bl*4+4)
    const int bo = tid >> 3;
    const int bl = tid & 7;

    float acc[2][8][4];
    #pragma unroll
    for (int mh = 0; mh < 2; mh++)
        #pragma unroll
        for (int nn = 0; nn < 8; nn++)
            #pragma unroll
            for (int e = 0; e < 4; e++) acc[mh][nn][e] = 0.0f;

    __syncthreads();

    // ldmatrix frag base addresses (bytes, shared space)
    const uint32_t tile0 = sbase + TILE_OFF;
    const uint32_t a_off = (uint32_t)((wm * 32 + (lane & 15)) * RSW_B + ((lane >> 4) << 4));
    const uint32_t b_off = (uint32_t)(A_BYTES
                         + (wn * 64 + ((lane >> 4) << 3) + (lane & 7)) * RSW_B
                         + (((lane >> 3) & 1) << 4));

    auto produce = [&](int i) {
        const int c0 = i * BK;
        const uint32_t SB = tile0 + (uint32_t)((i & 1) * STAGE_B);
        // ---- A: 2 waves x 4 channels ----
        const uint32_t a_st = SB + (uint32_t)(pxl * RSW_B + aq * 16);
        #pragma unroll
        for (int w = 0; w < 2; w++) {
            float2 q0[4], q1[4];
            #pragma unroll
            for (int e = 0; e < 4; e++) {
                const int c = c0 + aq * 8 + w * 4 + e;
                const float* xp = xb + (size_t)c * (HH * WW);
                q0[e] = *reinterpret_cast<const float2*>(xp);
                q1[e] = *reinterpret_cast<const float2*>(xp + WW);
            }
            float v[4];
            #pragma unroll
            for (int e = 0; e < 4; e++) {
                const int c = c0 + aq * 8 + w * 4 + e;
                const float sc = s_scale[c], sh = s_shift[c];
                v[e] = 0.25f * (fmaxf(fmaf(q0[e].x, sc, sh), 0.0f)
                              + fmaxf(fmaf(q0[e].y, sc, sh), 0.0f)
                              + fmaxf(fmaf(q1[e].x, sc, sh), 0.0f)
                              + fmaxf(fmaf(q1[e].y, sc, sh), 0.0f));
            }
            uint32_t h0, l0, h1, l1;
            split2(v[0], v[1], h0, l0);
            split2(v[2], v[3], h1, l1);
            sts64(a_st + w * 8, h0, h1);
            sts64(a_st + w * 8 + LO_B, l0, l1);
        }
        // ---- B: 2 waves x 4 rows ----
        #pragma unroll
        for (int w = 0; w < 2; w++) {
            float4 bw[4];
            #pragma unroll
            for (int p = 0; p < 4; p++) {
                const int o = bo + (w * 4 + p) * 32;
                bw[p] = *reinterpret_cast<const float4*>(conv_w + (size_t)o * CIN + c0 + bl * 4);
            }
            #pragma unroll
            for (int p = 0; p < 4; p++) {
                const int o = bo + (w * 4 + p) * 32;
                uint32_t h0, l0, h1, l1;
                split2(bw[p].x, bw[p].y, h0, l0);
                split2(bw[p].z, bw[p].w, h1, l1);
                const uint32_t b_st = SB + (uint32_t)(A_BYTES + o * RSW_B + bl * 8);
                sts64(b_st, h0, h1);
                sts64(b_st + LO_B, l0, l1);
            }
        }
    };

    auto compute = [&](int i) {
        const uint32_t SB = tile0 + (uint32_t)((i & 1) * STAGE_B);
        const uint32_t aA = SB + a_off;
        const uint32_t aB = SB + b_off;
        #pragma unroll
        for (int ks = 0; ks < 2; ks++) {
            uint32_t ah[2][4], al[2][4];
            #pragma unroll
            for (int mh = 0; mh < 2; mh++) {
                const uint32_t aa = aA + (uint32_t)(mh * 16 * RSW_B + ks * 32);
                LDMX4(ah[mh], aa);
                LDMX4(al[mh], aa + LO_B);
            }
            #pragma unroll
            for (int p = 0; p < 4; p++) {
                uint32_t bh[4], blo[4];
                const uint32_t ba = aB + (uint32_t)(p * 16 * RSW_B + ks * 32);
                LDMX4(bh, ba);
                LDMX4(blo, ba + LO_B);
                #pragma unroll
                for (int mh = 0; mh < 2; mh++) {
                    MMA_BF16(acc[mh][2 * p],     ah[mh], bh[0],  bh[1]);
                    MMA_BF16(acc[mh][2 * p],     ah[mh], blo[0], blo[1]);
                    MMA_BF16(acc[mh][2 * p],     al[mh], bh[0],  bh[1]);
                    MMA_BF16(acc[mh][2 * p + 1], ah[mh], bh[2],  bh[3]);
                    MMA_BF16(acc[mh][2 * p + 1], ah[mh], blo[2], blo[3]);
                    MMA_BF16(acc[mh][2 * p + 1], al[mh], bh[2],  bh[3]);
                }
            }
        }
    };

    produce(0);
    __syncthreads();

    #pragma unroll 1
    for (int i = 0; i < NCH; i++) {
        if (i + 1 < NCH) produce(i + 1);
        compute(i);
        __syncthreads();
    }

    // ---- epilogue ----
    const int fr = lane >> 2;
    const int q2 = (lane & 3) * 2;
    #pragma unroll
    for (int mh = 0; mh < 2; mh++) {
        #pragma unroll
        for (int half = 0; half < 2; half++) {
            const int m  = m0 + wm * 32 + mh * 16 + fr + half * 8;
            const int im = m / PIX;
            const int px = m % PIX;
            float* ob = out + (size_t)im * (COUT * PIX) + px;
            #pragma unroll
            for (int nn = 0; nn < 8; nn++) {
                const int n = wn * 64 + nn * 8 + q2;
                ob[(size_t)n * PIX]       = acc[mh][nn][half * 2];
                ob[(size_t)(n + 1) * PIX] = acc[mh][nn][half * 2 + 1];
            }
        }
    }
}

extern "C" void kernel_launch(void* const* d_in, const int* in_sizes, int n_in,
                              void* d_out, int out_size)
{
    const float* x      = (const float*)d_in[0];
    const float* bn_w   = (const float*)d_in[1];
    const float* bn_b   = (const float*)d_in[2];
    const float* bn_m   = (const float*)d_in[3];
    const float* bn_v   = (const float*)d_in[4];
    const float* conv_w = (const float*)d_in[5];
    float* out = (float*)d_out;

    cudaFuncSetAttribute(transition_hmma2_kernel,
                         cudaFuncAttributeMaxDynamicSharedMemorySize, SM_TOTAL);
    transition_hmma2_kernel<<<M_TOTAL / MT, 256, SM_TOTAL>>>(
        x, bn_w, bn_b, bn_m, bn_v, conv_w, out);
}

// round 6
// speedup vs baseline: 2.0025x; 1.1171x over previous
#include <cuda_runtime.h>
#include <cuda_bf16.h>
#include <cstdint>

// TransitionLayer: BN(eval)+ReLU+1x1conv(512->256)+avgpool2x2, NCHW fp32.
// pool(conv(act)) == conv(pool(act)) -> GEMM M=50176, K=512, N=256.
// R6: B prepacked once (kernel 1) into bf16 hi/lo, *fragment-major* layout ->
//     main kernel reads B frags by LDG straight from L2 (no B smem, no B math).
//     A path unchanged (smem + ldmatrix). HMMA bf16 3-term split.

#define BN_EPS 1e-5f

constexpr int CIN  = 512;
constexpr int HH   = 56;
constexpr int WW   = 56;
constexpr int COUT = 256;
constexpr int PP   = 28;
constexpr int PIX  = PP * PP;           // 784
constexpr int M_TOTAL = 64 * PIX;       // 50176
constexpr int MT   = 64;
constexpr int BK   = 32;
constexpr int NCH  = CIN / BK;          // 16

// A smem row: 144B stride, hi bf16 x32 at [0,64), lo at [64,128), pad 16B
constexpr int RSW_B   = 144;
constexpr int LO_B    = 64;
constexpr int A_BYTES = MT * RSW_B;          // 9216
constexpr int TILE_OFF = 4096;
constexpr int SM_TOTAL = TILE_OFF + 2 * A_BYTES;   // 22528 B

// Prepacked B: [chunk i][ks (2)][nb (32)][lane (32)] -> uint2 {b0,b1}
constexpr int BUNITS = NCH * 2 * 32 * 32;    // 32768
__device__ __align__(16) uint2 g_Bhi[BUNITS];
__device__ __align__(16) uint2 g_Blo[BUNITS];

#define MMA_BF16(C, A, B0, B1)                                               \
    asm volatile("mma.sync.aligned.m16n8k16.row.col.f32.bf16.bf16.f32 "      \
                 "{%0,%1,%2,%3}, {%4,%5,%6,%7}, {%8,%9}, {%0,%1,%2,%3};"     \
                 : "+f"((C)[0]), "+f"((C)[1]), "+f"((C)[2]), "+f"((C)[3])    \
                 : "r"((A)[0]), "r"((A)[1]), "r"((A)[2]), "r"((A)[3]),       \
                   "r"(B0), "r"(B1))

#define LDMX4(R, ADDR)                                                       \
    asm volatile("ldmatrix.sync.aligned.m8n8.x4.shared.b16 {%0,%1,%2,%3}, [%4];" \
                 : "=r"((R)[0]), "=r"((R)[1]), "=r"((R)[2]), "=r"((R)[3])    \
                 : "r"(ADDR))

__device__ __forceinline__ uint32_t smem_u32(const void* p) {
    uint32_t a;
    asm("{ .reg .u64 t; cvta.to.shared.u64 t, %1; cvt.u32.u64 %0, t; }" : "=r"(a) : "l"(p));
    return a;
}
__device__ __forceinline__ void split2(float v0, float v1, uint32_t& hi, uint32_t& lo) {
    __nv_bfloat16 h0 = __float2bfloat16_rn(v0);
    __nv_bfloat16 h1 = __float2bfloat16_rn(v1);
    __nv_bfloat16 l0 = __float2bfloat16_rn(v0 - __bfloat162float(h0));
    __nv_bfloat16 l1 = __float2bfloat16_rn(v1 - __bfloat162float(h1));
    hi = (uint32_t)__bfloat16_as_ushort(h0) | ((uint32_t)__bfloat16_as_ushort(h1) << 16);
    lo = (uint32_t)__bfloat16_as_ushort(l0) | ((uint32_t)__bfloat16_as_ushort(l1) << 16);
}
__device__ __forceinline__ void sts64(uint32_t addr, uint32_t a, uint32_t b) {
    asm volatile("st.shared.v2.b32 [%0], {%1,%2};" :: "r"(addr), "r"(a), "r"(b) : "memory");
}

// ---------------- kernel 1: prepack B fragments ----------------
__global__ void prepack_B(const float* __restrict__ conv_w)
{
    const int idx = blockIdx.x * 256 + threadIdx.x;
    if (idx >= BUNITS) return;
    const int lane = idx & 31;
    const int nb   = (idx >> 5) & 31;
    const int ks   = (idx >> 10) & 1;
    const int i    = idx >> 11;
    const int n  = nb * 8 + (lane >> 2);
    const int k0 = i * BK + ks * 16 + (lane & 3) * 2;
    const float* wr = conv_w + (size_t)n * CIN;
    uint32_t h0, l0, h1, l1;
    split2(wr[k0],     wr[k0 + 1], h0, l0);   // b0: (k0, k0+1)
    split2(wr[k0 + 8], wr[k0 + 9], h1, l1);   // b1: (k0+8, k0+9)
    g_Bhi[idx] = make_uint2(h0, h1);
    g_Blo[idx] = make_uint2(l0, l1);
}

// ---------------- kernel 2: main ----------------
__global__ __launch_bounds__(256, 2)
void transition_hmma3_kernel(const float* __restrict__ x,
                             const float* __restrict__ bn_w,
                             const float* __restrict__ bn_b,
                             const float* __restrict__ bn_m,
                             const float* __restrict__ bn_v,
                             float* __restrict__ out)
{
    extern __shared__ __align__(16) uint32_t sm[];
    float* s_scale = reinterpret_cast<float*>(sm);
    float* s_shift = reinterpret_cast<float*>(sm) + 512;
    const uint32_t sbase = smem_u32(sm);

    const int tid  = threadIdx.x;
    const int wid  = tid >> 5;
    const int lane = tid & 31;
    const int wm   = wid & 1;          // rows wm*32..+32
    const int wn   = wid >> 1;         // cols wn*64..+64

    for (int c = tid; c < CIN; c += 256) {
        float inv = rsqrtf(bn_v[c] + BN_EPS);
        float sc  = bn_w[c] * inv;
        s_scale[c] = sc;
        s_shift[c] = bn_b[c] - bn_m[c] * sc;
    }

    const int m0 = blockIdx.x * MT;

    // A producer mapping
    const int pxl = tid >> 2;
    const int aq  = tid & 3;
    const int mg  = m0 + pxl;
    const int img = mg / PIX;
    const int pr  = mg % PIX;
    const float* xb = x + (size_t)img * (CIN * HH * WW)
                        + (size_t)(2 * (pr / PP)) * WW + 2 * (pr % PP);

    float acc[2][8][4];
    #pragma unroll
    for (int mh = 0; mh < 2; mh++)
        #pragma unroll
        for (int nn = 0; nn < 8; nn++)
            #pragma unroll
            for (int e = 0; e < 4; e++) acc[mh][nn][e] = 0.0f;

    __syncthreads();

    const uint32_t tile0 = sbase + TILE_OFF;
    const uint32_t a_off = (uint32_t)((wm * 32 + (lane & 15)) * RSW_B + ((lane >> 4) << 4));
    // B frag pointers: this warp's nb base = wn*8; unit stride = 32 uint2
    const uint2* bh_base = g_Bhi + (size_t)(wn * 8) * 32 + lane;
    const uint2* bl_base = g_Blo + (size_t)(wn * 8) * 32 + lane;

    auto produce = [&](int i) {
        const int c0 = i * BK;
        const uint32_t a_st = tile0 + (uint32_t)((i & 1) * A_BYTES + pxl * RSW_B + aq * 16);
        #pragma unroll
        for (int w = 0; w < 2; w++) {
            float2 q0[4], q1[4];
            #pragma unroll
            for (int e = 0; e < 4; e++) {
                const int c = c0 + aq * 8 + w * 4 + e;
                const float* xp = xb + (size_t)c * (HH * WW);
                q0[e] = *reinterpret_cast<const float2*>(xp);
                q1[e] = *reinterpret_cast<const float2*>(xp + WW);
            }
            float v[4];
            #pragma unroll
            for (int e = 0; e < 4; e++) {
                const int c = c0 + aq * 8 + w * 4 + e;
                const float sc = s_scale[c], sh = s_shift[c];
                v[e] = 0.25f * (fmaxf(fmaf(q0[e].x, sc, sh), 0.0f)
                              + fmaxf(fmaf(q0[e].y, sc, sh), 0.0f)
                              + fmaxf(fmaf(q1[e].x, sc, sh), 0.0f)
                              + fmaxf(fmaf(q1[e].y, sc, sh), 0.0f));
            }
            uint32_t h0, l0, h1, l1;
            split2(v[0], v[1], h0, l0);
            split2(v[2], v[3], h1, l1);
            sts64(a_st + w * 8, h0, h1);
            sts64(a_st + w * 8 + LO_B, l0, l1);
        }
    };

    auto compute = [&](int i) {
        const uint32_t aA = tile0 + (uint32_t)((i & 1) * A_BYTES) + a_off;
        #pragma unroll
        for (int ks = 0; ks < 2; ks++) {
            uint32_t ah[2][4], al[2][4];
            #pragma unroll
            for (int mh = 0; mh < 2; mh++) {
                const uint32_t aa = aA + (uint32_t)(mh * 16 * RSW_B + ks * 32);
                LDMX4(ah[mh], aa);
                LDMX4(al[mh], aa + LO_B);
            }
            const uint2* bh = bh_base + (size_t)(i * 2 + ks) * (32 * 32);
            const uint2* bl = bl_base + (size_t)(i * 2 + ks) * (32 * 32);
            #pragma unroll
            for (int nn = 0; nn < 8; nn++) {
                const uint2 h = __ldg(bh + nn * 32);
                const uint2 l = __ldg(bl + nn * 32);
                #pragma unroll
                for (int mh = 0; mh < 2; mh++) {
                    MMA_BF16(acc[mh][nn], ah[mh], h.x, h.y);
                    MMA_BF16(acc[mh][nn], ah[mh], l.x, l.y);
                    MMA_BF16(acc[mh][nn], al[mh], h.x, h.y);
                }
            }
        }
    };

    produce(0);
    __syncthreads();

    #pragma unroll 1
    for (int i = 0; i < NCH; i++) {
        if (i + 1 < NCH) produce(i + 1);
        compute(i);
        __syncthreads();
    }

    // epilogue
    const int fr = lane >> 2;
    const int q2 = (lane & 3) * 2;
    #pragma unroll
    for (int mh = 0; mh < 2; mh++) {
        #pragma unroll
        for (int half = 0; half < 2; half++) {
            const int m  = m0 + wm * 32 + mh * 16 + fr + half * 8;
            const int im = m / PIX;
            const int px = m % PIX;
            float* ob = out + (size_t)im * (COUT * PIX) + px;
            #pragma unroll
            for (int nn = 0; nn < 8; nn++) {
                const int n = wn * 64 + nn * 8 + q2;
                ob[(size_t)n * PIX]       = acc[mh][nn][half * 2];
                ob[(size_t)(n + 1) * PIX] = acc[mh][nn][half * 2 + 1];
            }
        }
    }
}

extern "C" void kernel_launch(void* const* d_in, const int* in_sizes, int n_in,
                              void* d_out, int out_size)
{
    const float* x      = (const float*)d_in[0];
    const float* bn_w   = (const float*)d_in[1];
    const float* bn_b   = (const float*)d_in[2];
    const float* bn_m   = (const float*)d_in[3];
    const float* bn_v   = (const float*)d_in[4];
    const float* conv_w = (const float*)d_in[5];
    float* out = (float*)d_out;

    prepack_B<<<(BUNITS + 255) / 256, 256>>>(conv_w);

    cudaFuncSetAttribute(transition_hmma3_kernel,
                         cudaFuncAttributeMaxDynamicSharedMemorySize, SM_TOTAL);
    transition_hmma3_kernel<<<M_TOTAL / MT, 256, SM_TOTAL>>>(
        x, bn_w, bn_b, bn_m, bn_v, out);
}

// round 7
// speedup vs baseline: 2.3636x; 1.1803x over previous
#include <cuda_runtime.h>
#include <cuda_fp16.h>
#include <cstdint>

// TransitionLayer: BN(eval)+ReLU+1x1conv(512->256)+avgpool2x2, NCHW fp32.
// pool(conv(act)) == conv(pool(act)) -> GEMM M=50176, K=512, N=256.
// R7: fp16 HMMA, asymmetric split: B = hi+lo fp16 (prepacked, exact to 22 bits),
//     A = single fp16. 2 MMAs per k16 (was 3). B frags as uint4 (1 LDG.128).
//     x loads for next chunk interleaved between compute k-halves.

#define BN_EPS 1e-5f

constexpr int CIN  = 512;
constexpr int HH   = 56;
constexpr int WW   = 56;
constexpr int COUT = 256;
constexpr int PP   = 28;
constexpr int PIX  = PP * PP;           // 784
constexpr int M_TOTAL = 64 * PIX;       // 50176
constexpr int MT   = 64;
constexpr int BK   = 32;
constexpr int NCH  = CIN / BK;          // 16

// A smem: fp16 hi only. row = 80B (64B data + 16B pad), 16B-aligned rows;
// ldmatrix phase banks: starts (20*r)%32 tile all 32 banks -> conflict-free.
constexpr int ARSB    = 80;
constexpr int A_BYTES = MT * ARSB;           // 5120 per stage
constexpr int TILE_OFF = 4096;
constexpr int SM_TOTAL = TILE_OFF + 2 * A_BYTES;   // 14336

// Prepacked B frags: [i*2+ks][nb][lane] -> uint4 {bhi0,bhi1,blo0,blo1}
constexpr int BUNITS = NCH * 2 * 32 * 32;    // 32768
__device__ __align__(16) uint4 g_Bfrag[BUNITS];

#define MMA_F16(C, A, B0, B1)                                                \
    asm volatile("mma.sync.aligned.m16n8k16.row.col.f32.f16.f16.f32 "        \
                 "{%0,%1,%2,%3}, {%4,%5,%6,%7}, {%8,%9}, {%0,%1,%2,%3};"     \
                 : "+f"((C)[0]), "+f"((C)[1]), "+f"((C)[2]), "+f"((C)[3])    \
                 : "r"((A)[0]), "r"((A)[1]), "r"((A)[2]), "r"((A)[3]),       \
                   "r"(B0), "r"(B1))

#define LDMX4(R, ADDR)                                                       \
    asm volatile("ldmatrix.sync.aligned.m8n8.x4.shared.b16 {%0,%1,%2,%3}, [%4];" \
                 : "=r"((R)[0]), "=r"((R)[1]), "=r"((R)[2]), "=r"((R)[3])    \
                 : "r"(ADDR))

__device__ __forceinline__ uint32_t smem_u32(const void* p) {
    uint32_t a;
    asm("{ .reg .u64 t; cvta.to.shared.u64 t, %1; cvt.u32.u64 %0, t; }" : "=r"(a) : "l"(p));
    return a;
}
__device__ __forceinline__ void split2_f16(float v0, float v1, uint32_t& hi, uint32_t& lo) {
    __half h0 = __float2half_rn(v0);
    __half h1 = __float2half_rn(v1);
    __half l0 = __float2half_rn(v0 - __half2float(h0));
    __half l1 = __float2half_rn(v1 - __half2float(h1));
    hi = (uint32_t)__half_as_ushort(h0) | ((uint32_t)__half_as_ushort(h1) << 16);
    lo = (uint32_t)__half_as_ushort(l0) | ((uint32_t)__half_as_ushort(l1) << 16);
}
__device__ __forceinline__ uint32_t pack2_f16(float v0, float v1) {
    __half h0 = __float2half_rn(v0);
    __half h1 = __float2half_rn(v1);
    return (uint32_t)__half_as_ushort(h0) | ((uint32_t)__half_as_ushort(h1) << 16);
}
__device__ __forceinline__ void sts64(uint32_t addr, uint32_t a, uint32_t b) {
    asm volatile("st.shared.v2.b32 [%0], {%1,%2};" :: "r"(addr), "r"(a), "r"(b) : "memory");
}

// ---------------- kernel 1: prepack B (hi/lo fp16, fragment-major) ----------------
__global__ void prepack_B(const float* __restrict__ conv_w)
{
    const int idx = blockIdx.x * 256 + threadIdx.x;
    if (idx >= BUNITS) return;
    const int lane = idx & 31;
    const int nb   = (idx >> 5) & 31;
    const int kc   = idx >> 10;            // i*2+ks (0..31)
    const int n  = nb * 8 + (lane >> 2);
    const int k0 = kc * 16 + (lane & 3) * 2;
    const float* wr = conv_w + (size_t)n * CIN;
    uint32_t h0, l0, h1, l1;
    split2_f16(wr[k0],     wr[k0 + 1], h0, l0);   // b0: (k0, k0+1)
    split2_f16(wr[k0 + 8], wr[k0 + 9], h1, l1);   // b1: (k0+8, k0+9)
    g_Bfrag[idx] = make_uint4(h0, h1, l0, l1);
}

// ---------------- kernel 2: main ----------------
__global__ __launch_bounds__(256, 2)
void transition_hmma4_kernel(const float* __restrict__ x,
                             const float* __restrict__ bn_w,
                             const float* __restrict__ bn_b,
                             const float* __restrict__ bn_m,
                             const float* __restrict__ bn_v,
                             float* __restrict__ out)
{
    extern __shared__ __align__(16) uint32_t sm[];
    float* s_scale = reinterpret_cast<float*>(sm);
    float* s_shift = reinterpret_cast<float*>(sm) + 512;
    const uint32_t sbase = smem_u32(sm);

    const int tid  = threadIdx.x;
    const int wid  = tid >> 5;
    const int lane = tid & 31;
    const int wm   = wid & 1;          // rows wm*32..+32
    const int wn   = wid >> 1;         // cols wn*64..+64

    for (int c = tid; c < CIN; c += 256) {
        float inv = rsqrtf(bn_v[c] + BN_EPS);
        float sc  = bn_w[c] * inv;
        s_scale[c] = sc;
        s_shift[c] = bn_b[c] - bn_m[c] * sc;
    }

    const int m0 = blockIdx.x * MT;

    // producer mapping: pxl row (0..63), aq covers channels aq*8..+8 (2 waves of 4)
    const int pxl = tid >> 2;
    const int aq  = tid & 3;
    const int mg  = m0 + pxl;
    const int img = mg / PIX;
    const int pr  = mg % PIX;
    const float* xb = x + (size_t)img * (CIN * HH * WW)
                        + (size_t)(2 * (pr / PP)) * WW + 2 * (pr % PP);

    float acc[2][8][4];
    #pragma unroll
    for (int mh = 0; mh < 2; mh++)
        #pragma unroll
        for (int nn = 0; nn < 8; nn++)
            #pragma unroll
            for (int e = 0; e < 4; e++) acc[mh][nn][e] = 0.0f;

    __syncthreads();

    const uint32_t tile0 = sbase + TILE_OFF;
    const uint32_t a_ldm = (uint32_t)((wm * 32 + (lane & 15)) * ARSB + ((lane >> 4) << 4));
    const uint32_t a_st  = (uint32_t)(pxl * ARSB + aq * 16);
    const uint4* bbase = g_Bfrag + (size_t)(wn * 8) * 32 + lane;

    float2 q0[4], q1[4];   // one 4-channel wave of raw x

    auto ldg_wave = [&](int i, int w) {
        const int c0 = i * BK + aq * 8 + w * 4;
        #pragma unroll
        for (int e = 0; e < 4; e++) {
            const float* xp = xb + (size_t)(c0 + e) * (HH * WW);
            q0[e] = *reinterpret_cast<const float2*>(xp);
            q1[e] = *reinterpret_cast<const float2*>(xp + WW);
        }
    };
    auto cvt_sts_wave = [&](int i, int w) {
        const int c0 = i * BK + aq * 8 + w * 4;
        float v[4];
        #pragma unroll
        for (int e = 0; e < 4; e++) {
            const float sc = s_scale[c0 + e], sh = s_shift[c0 + e];
            v[e] = 0.25f * (fmaxf(fmaf(q0[e].x, sc, sh), 0.0f)
                          + fmaxf(fmaf(q0[e].y, sc, sh), 0.0f)
                          + fmaxf(fmaf(q1[e].x, sc, sh), 0.0f)
                          + fmaxf(fmaf(q1[e].y, sc, sh), 0.0f));
        }
        const uint32_t st = tile0 + (uint32_t)((i & 1) * A_BYTES) + a_st + (uint32_t)(w * 8);
        sts64(st, pack2_f16(v[0], v[1]), pack2_f16(v[2], v[3]));
    };

    auto compute_ks = [&](int i, int ks) {
        const uint32_t aa = tile0 + (uint32_t)((i & 1) * A_BYTES) + a_ldm + (uint32_t)(ks * 32);
        uint32_t ah[2][4];
        LDMX4(ah[0], aa);
        LDMX4(ah[1], aa + 16 * ARSB);
        const uint4* bp = bbase + (size_t)(i * 2 + ks) * (32 * 32);
        #pragma unroll
        for (int nn = 0; nn < 8; nn++) {
            const uint4 b = __ldg(bp + nn * 32);
            #pragma unroll
            for (int mh = 0; mh < 2; mh++) {
                MMA_F16(acc[mh][nn], ah[mh], b.x, b.y);   // A * Bhi
                MMA_F16(acc[mh][nn], ah[mh], b.z, b.w);   // A * Blo
            }
        }
    };

    // prologue: fill chunk 0
    ldg_wave(0, 0); cvt_sts_wave(0, 0);
    ldg_wave(0, 1); cvt_sts_wave(0, 1);
    __syncthreads();

    #pragma unroll 1
    for (int i = 0; i < NCH; i++) {
        const bool more = (i + 1 < NCH);
        if (more) ldg_wave(i + 1, 0);
        compute_ks(i, 0);
        if (more) { cvt_sts_wave(i + 1, 0); ldg_wave(i + 1, 1); }
        compute_ks(i, 1);
        if (more) cvt_sts_wave(i + 1, 1);
        __syncthreads();
    }

    // epilogue
    const int fr = lane >> 2;
    const int q2 = (lane & 3) * 2;
    #pragma unroll
    for (int mh = 0; mh < 2; mh++) {
        #pragma unroll
        for (int half = 0; half < 2; half++) {
            const int m  = m0 + wm * 32 + mh * 16 + fr + half * 8;
            const int im = m / PIX;
            const int px = m % PIX;
            float* ob = out + (size_t)im * (COUT * PIX) + px;
            #pragma unroll
            for (int nn = 0; nn < 8; nn++) {
                const int n = wn * 64 + nn * 8 + q2;
                ob[(size_t)n * PIX]       = acc[mh][nn][half * 2];
                ob[(size_t)(n + 1) * PIX] = acc[mh][nn][half * 2 + 1];
            }
        }
    }
}

extern "C" void kernel_launch(void* const* d_in, const int* in_sizes, int n_in,
                              void* d_out, int out_size)
{
    const float* x      = (const float*)d_in[0];
    const float* bn_w   = (const float*)d_in[1];
    const float* bn_b   = (const float*)d_in[2];
    const float* bn_m   = (const float*)d_in[3];
    const float* bn_v   = (const float*)d_in[4];
    const float* conv_w = (const float*)d_in[5];
    float* out = (float*)d_out;

    prepack_B<<<(BUNITS + 255) / 256, 256>>>(conv_w);

    cudaFuncSetAttribute(transition_hmma4_kernel,
                         cudaFuncAttributeMaxDynamicSharedMemorySize, SM_TOTAL);
    transition_hmma4_kernel<<<M_TOTAL / MT, 256, SM_TOTAL>>>(
        x, bn_w, bn_b, bn_m, bn_v, out);
}